// round 3
// baseline (speedup 1.0000x reference)
#include <cuda_runtime.h>

#define MROWS   512   // rows of weight / output dim
#define KDIM    20    // motion dim
#define OUT_DIM 512
#define BTILE   256   // batch rows per block in GEMM
#define GTHREADS 256  // 8 warps: 256 threads x 2 outputs = 512 outputs

// Q transposed: g_Qt[k*512 + o] = Q[o][k]
__device__ float g_Qt[KDIM * OUT_DIM];

// ---------------------------------------------------------------------------
// helpers
// ---------------------------------------------------------------------------
__device__ __forceinline__ float blockReduceSum(float x, float* red) {
    int lane = threadIdx.x & 31;
    int wid  = threadIdx.x >> 5;
    #pragma unroll
    for (int off = 16; off; off >>= 1) x += __shfl_xor_sync(0xffffffffu, x, off);
    if (lane == 0) red[wid] = x;
    __syncthreads();
    float s = (lane < 16) ? red[lane] : 0.f;   // 16 warps -> 16 partials
    #pragma unroll
    for (int off = 8; off; off >>= 1) s += __shfl_xor_sync(0xffffffffu, s, off);
    s = __shfl_sync(0xffffffffu, s, 0);
    __syncthreads();                            // protect red for next call
    return s;
}

__device__ __forceinline__ unsigned long long pack2(float lo, float hi) {
    unsigned long long r;
    asm("mov.b64 %0, {%1, %2};" : "=l"(r) : "f"(lo), "f"(hi));
    return r;
}

__device__ __forceinline__ unsigned long long ffma2(unsigned long long a,
                                                    unsigned long long b,
                                                    unsigned long long c) {
    unsigned long long d;
    asm("fma.rn.f32x2 %0, %1, %2, %3;" : "=l"(d) : "l"(a), "l"(b), "l"(c));
    return d;
}

__device__ __forceinline__ float hadd2(unsigned long long a) {
    float lo, hi;
    asm("mov.b64 {%0, %1}, %2;" : "=f"(lo), "=f"(hi) : "l"(a));
    return lo + hi;
}

// ---------------------------------------------------------------------------
// Householder QR (LAPACK sgeqr2 + sorg2r conventions) of W + 1e-8, W: [512,20]
// Single block, 512 threads (one per row). Writes Q^T to g_Qt.
// ---------------------------------------------------------------------------
__global__ void qr_kernel(const float* __restrict__ W) {
    __shared__ float sA[KDIM][MROWS];   // column-major: sA[c][t] = A[t][c]
    __shared__ float sV[MROWS];
    __shared__ float sTau[KDIM];
    __shared__ float sRed[16];

    const int t    = threadIdx.x;
    const int lane = t & 31;
    const int wid  = t >> 5;

    #pragma unroll
    for (int c = 0; c < KDIM; ++c)
        sA[c][t] = W[t * KDIM + c] + 1e-8f;
    __syncthreads();

    // ---- factorization (geqr2) ----
    for (int j = 0; j < KDIM; ++j) {
        float a  = sA[j][t];
        float sq = (t > j) ? a * a : 0.f;
        float xnorm2 = blockReduceSum(sq, sRed);
        float alpha  = sA[j][j];
        float beta   = -copysignf(sqrtf(alpha * alpha + xnorm2), alpha); // LAPACK sign
        float tau    = (beta - alpha) / beta;
        float inv    = 1.f / (alpha - beta);
        float v      = (t == j) ? 1.f : ((t > j) ? a * inv : 0.f);
        sV[t] = v;
        if (t == j)      { sTau[j] = tau; sA[j][j] = beta; }
        else if (t > j)  { sA[j][t] = v; }   // store reflector
        __syncthreads();

        // trailing update: one warp per column
        for (int c = j + 1 + wid; c < KDIM; c += 16) {
            float w = 0.f;
            #pragma unroll
            for (int i = lane; i < MROWS; i += 32) w += sV[i] * sA[c][i];
            #pragma unroll
            for (int off = 16; off; off >>= 1) w += __shfl_xor_sync(0xffffffffu, w, off);
            float tw = sTau[j] * w;
            #pragma unroll
            for (int i = lane; i < MROWS; i += 32) sA[c][i] -= tw * sV[i];
        }
        __syncthreads();
    }

    // ---- form Q in place (org2r) ----
    for (int j = KDIM - 1; j >= 0; --j) {
        float tau = sTau[j];
        float vt  = (t == j) ? 1.f : ((t > j) ? sA[j][t] : 0.f);
        sV[t] = vt;
        __syncthreads();

        for (int c = j + 1 + wid; c < KDIM; c += 16) {
            float w = 0.f;
            #pragma unroll
            for (int i = lane; i < MROWS; i += 32) w += sV[i] * sA[c][i];
            #pragma unroll
            for (int off = 16; off; off >>= 1) w += __shfl_xor_sync(0xffffffffu, w, off);
            float tw = tau * w;
            #pragma unroll
            for (int i = lane; i < MROWS; i += 32) sA[c][i] -= tw * sV[i];
        }
        __syncthreads();
        sA[j][t] = (t == j) ? (1.f - tau) : ((t > j) ? -tau * vt : 0.f);
        __syncthreads();
    }

    // store Q^T (coalesced per column)
    #pragma unroll
    for (int k = 0; k < KDIM; ++k)
        g_Qt[k * OUT_DIM + t] = sA[k][t];
}

// ---------------------------------------------------------------------------
// out[b][o] = sum_k input[b][k] * Q[o][k]
// 256 threads, 2 outputs/thread (Q = 20 u64 regs), 2 rows per iteration so
// there are 4 independent acc chains (FFMA2 lat=4). Per thread per row-pair:
// 10 LDS.128, 40 FFMA2, 4 hadd, 2 STG.64.
// ---------------------------------------------------------------------------
__global__ void __launch_bounds__(GTHREADS)
gemm_kernel(const float* __restrict__ input, float* __restrict__ out, int batch) {
    __shared__ float sIn[BTILE * KDIM];   // 20 KB

    const int tid = threadIdx.x;
    const long long b0 = (long long)blockIdx.x * BTILE;
    int rows = (batch - b0 < BTILE) ? (int)(batch - b0) : BTILE;

    // this thread's Q columns (o = 2*tid, 2*tid+1), paired along k
    unsigned long long q0[KDIM / 2], q1[KDIM / 2];
    #pragma unroll
    for (int p = 0; p < KDIM / 2; ++p) {
        float2 e = reinterpret_cast<const float2*>(g_Qt + (2 * p)     * OUT_DIM)[tid];
        float2 o = reinterpret_cast<const float2*>(g_Qt + (2 * p + 1) * OUT_DIM)[tid];
        q0[p] = pack2(e.x, o.x);
        q1[p] = pack2(e.y, o.y);
    }

    // stage input tile (raw copy, float4-vectorized)
    const float4* inBlk = reinterpret_cast<const float4*>(input + b0 * KDIM);
    float4* sIn4 = reinterpret_cast<float4*>(sIn);
    const int n4 = rows * KDIM / 4;            // rows*5 float4s
    for (int i = tid; i < n4; i += GTHREADS) {
        sIn4[i] = inBlk[i];
    }
    __syncthreads();

    float2* outp = reinterpret_cast<float2*>(out + b0 * OUT_DIM) + tid;

    int r = 0;
    #pragma unroll 2
    for (; r + 2 <= rows; r += 2) {
        const ulonglong2* rowA = reinterpret_cast<const ulonglong2*>(sIn + r * KDIM);
        const ulonglong2* rowB = reinterpret_cast<const ulonglong2*>(sIn + (r + 1) * KDIM);
        unsigned long long a0 = 0ull, a1 = 0ull;   // row r, outputs 0/1
        unsigned long long b0a = 0ull, b1a = 0ull; // row r+1, outputs 0/1
        #pragma unroll
        for (int p = 0; p < KDIM / 4; ++p) {   // 5 LDS.128 per row
            ulonglong2 xa = rowA[p];
            ulonglong2 xb = rowB[p];
            a0  = ffma2(xa.x, q0[2 * p],     a0);
            a1  = ffma2(xa.x, q1[2 * p],     a1);
            b0a = ffma2(xb.x, q0[2 * p],     b0a);
            b1a = ffma2(xb.x, q1[2 * p],     b1a);
            a0  = ffma2(xa.y, q0[2 * p + 1], a0);
            a1  = ffma2(xa.y, q1[2 * p + 1], a1);
            b0a = ffma2(xb.y, q0[2 * p + 1], b0a);
            b1a = ffma2(xb.y, q1[2 * p + 1], b1a);
        }
        float2 resA, resB;
        resA.x = hadd2(a0);  resA.y = hadd2(a1);
        resB.x = hadd2(b0a); resB.y = hadd2(b1a);
        outp[(long long)r       * (OUT_DIM / 2)] = resA;
        outp[(long long)(r + 1) * (OUT_DIM / 2)] = resB;
    }
    // odd tail row (not hit for batch % 2 == 0 tiles)
    if (r < rows) {
        const ulonglong2* row = reinterpret_cast<const ulonglong2*>(sIn + r * KDIM);
        unsigned long long a0 = 0ull, a1 = 0ull;
        #pragma unroll
        for (int p = 0; p < KDIM / 4; ++p) {
            ulonglong2 x = row[p];
            a0 = ffma2(x.x, q0[2 * p],     a0);
            a1 = ffma2(x.x, q1[2 * p],     a1);
            a0 = ffma2(x.y, q0[2 * p + 1], a0);
            a1 = ffma2(x.y, q1[2 * p + 1], a1);
        }
        float2 res;
        res.x = hadd2(a0); res.y = hadd2(a1);
        outp[(long long)r * (OUT_DIM / 2)] = res;
    }
}

// ---------------------------------------------------------------------------
extern "C" void kernel_launch(void* const* d_in, const int* in_sizes, int n_in,
                              void* d_out, int out_size) {
    const float* input  = (const float*)d_in[0];
    const float* weight = (const float*)d_in[1];
    int s0 = in_sizes[0], s1 = in_sizes[1];
    if (s0 < s1) {  // weight is the smaller tensor (512*20); be robust to order
        const float* tmp = input; input = weight; weight = tmp;
        int ts = s0; s0 = s1; s1 = ts;
    }
    const int batch = s0 / KDIM;

    qr_kernel<<<1, MROWS>>>(weight);

    const int grid = (batch + BTILE - 1) / BTILE;
    gemm_kernel<<<grid, GTHREADS>>>(input, (float*)d_out, batch);
}